// round 1
// baseline (speedup 1.0000x reference)
#include <cuda_runtime.h>
#include <math.h>

#define Bdim 256
#define Tdim 256
#define Ddim 128
#define Hdim 1024
#define Odim 64
#define BT (Bdim*Tdim)

// ---------------- scratch (device globals; no allocations allowed) ----------
__device__ float g_xmod[BT*Ddim];            // modified x  [BT, D]
__device__ float g_pre_z[67108864];          // [BT, H]
__device__ float g_pre_r[67108864];          // [BT, H]
__device__ float g_pre_h[67108864];          // [BT, H]
__device__ float g_gamma[67108864];          // [BT, H]
__device__ float g_hs[Bdim*Hdim];            // gamma-scaled hidden state
__device__ float g_h [Bdim*Hdim];            // hidden state (post-update)
__device__ float g_z [Bdim*Hdim];            // z gate
__device__ float g_rh[Bdim*Hdim];            // r * hs

// ---------------- elementwise: input decay --------------------------------
__global__ void k_xmod(const float* __restrict__ x, const float* __restrict__ delta,
                       const float* __restrict__ m, const float* __restrict__ wgx,
                       const float* __restrict__ bgx) {
    int i = blockIdx.x*blockDim.x + threadIdx.x;
    if (i >= BT*Ddim) return;
    int d = i & (Ddim-1);
    float dec = delta[i]*wgx[d] + bgx[d];
    float xr  = (1.0f - dec)*0.001f;
    g_xmod[i] = (m[i] > 0.0f) ? xr : x[i];
}

// ---------------- precompute GEMMs: pre_z/pre_r/pre_h/gamma_h -------------
// blockIdx.z selects output. For z/r/h: out = xmod@W + (1-m)@V + bias.
// For gamma: out = exp(-relu(m@Wg + bg)).
__global__ void k_pre(const float* __restrict__ m,
                      const float* __restrict__ Wz, const float* __restrict__ Vz, const float* __restrict__ bz,
                      const float* __restrict__ Wr, const float* __restrict__ Vr, const float* __restrict__ br,
                      const float* __restrict__ Wh, const float* __restrict__ Vh, const float* __restrict__ bh,
                      const float* __restrict__ Wg, const float* __restrict__ bg)
{
    __shared__ float4 As1[32][16];   // A1 transposed: [k][row/4]
    __shared__ float4 As2[32][16];   // (1-m) transposed
    __shared__ float4 Bs1[32][16];   // W tile [k][col/4]
    __shared__ float4 Bs2[32][16];   // V tile

    int which = blockIdx.z;
    const float* Bw; const float* Bv = nullptr; const float* bias; float* out;
    if      (which == 0) { Bw = Wz; Bv = Vz; bias = bz; out = g_pre_z; }
    else if (which == 1) { Bw = Wr; Bv = Vr; bias = br; out = g_pre_r; }
    else if (which == 2) { Bw = Wh; Bv = Vh; bias = bh; out = g_pre_h; }
    else                 { Bw = Wg;          bias = bg; out = g_gamma; }
    const bool dual = (which < 3);

    int tid = threadIdx.x;
    int tx = tid & 15, ty = tid >> 4;
    int row0 = blockIdx.y * 64;
    int col0 = blockIdx.x * 64;

    float acc1[4][4] = {};
    float acc2[4][4] = {};
    float* As1f = (float*)As1;
    float* As2f = (float*)As2;

    for (int kk = 0; kk < Ddim; kk += 32) {
        #pragma unroll
        for (int j = 0; j < 2; j++) {
            int li   = tid + 256*j;        // 0..511
            int arow = li >> 3;            // 8 float4 per 32-wide k row
            int k4   = (li & 7) * 4;
            int gidx = (row0 + arow)*Ddim + kk + k4;
            float4 am = *(const float4*)(&m[gidx]);
            if (dual) {
                float4 a1 = *(const float4*)(&g_xmod[gidx]);
                As1f[(k4+0)*64 + arow] = a1.x;
                As1f[(k4+1)*64 + arow] = a1.y;
                As1f[(k4+2)*64 + arow] = a1.z;
                As1f[(k4+3)*64 + arow] = a1.w;
                As2f[(k4+0)*64 + arow] = 1.0f - am.x;
                As2f[(k4+1)*64 + arow] = 1.0f - am.y;
                As2f[(k4+2)*64 + arow] = 1.0f - am.z;
                As2f[(k4+3)*64 + arow] = 1.0f - am.w;
            } else {
                As1f[(k4+0)*64 + arow] = am.x;
                As1f[(k4+1)*64 + arow] = am.y;
                As1f[(k4+2)*64 + arow] = am.z;
                As1f[(k4+3)*64 + arow] = am.w;
            }
        }
        #pragma unroll
        for (int j = 0; j < 2; j++) {
            int li = tid + 256*j;
            int brow = li >> 4;
            int bc4  = li & 15;
            Bs1[brow][bc4] = *(const float4*)(&Bw[(kk+brow)*Hdim + col0 + bc4*4]);
            if (dual)
                Bs2[brow][bc4] = *(const float4*)(&Bv[(kk+brow)*Hdim + col0 + bc4*4]);
        }
        __syncthreads();
        #pragma unroll
        for (int k = 0; k < 32; k++) {
            float4 a1 = As1[k][ty];
            float4 b1 = Bs1[k][tx];
            float av1[4] = {a1.x,a1.y,a1.z,a1.w};
            float bv1[4] = {b1.x,b1.y,b1.z,b1.w};
            #pragma unroll
            for (int i = 0; i < 4; i++)
                #pragma unroll
                for (int jj = 0; jj < 4; jj++)
                    acc1[i][jj] += av1[i]*bv1[jj];
            if (dual) {
                float4 a2 = As2[k][ty];
                float4 b2 = Bs2[k][tx];
                float av2[4] = {a2.x,a2.y,a2.z,a2.w};
                float bv2[4] = {b2.x,b2.y,b2.z,b2.w};
                #pragma unroll
                for (int i = 0; i < 4; i++)
                    #pragma unroll
                    for (int jj = 0; jj < 4; jj++)
                        acc2[i][jj] += av2[i]*bv2[jj];
            }
        }
        __syncthreads();
    }
    int row = row0 + ty*4;
    int col = col0 + tx*4;
    #pragma unroll
    for (int i = 0; i < 4; i++) {
        #pragma unroll
        for (int jj = 0; jj < 4; jj++) {
            float v = acc1[i][jj] + acc2[i][jj] + bias[col+jj];
            if (which == 3) v = expf(-fmaxf(0.0f, v));
            out[(size_t)(row+i)*Hdim + (col+jj)] = v;
        }
    }
}

__global__ void k_init() {
    int i = blockIdx.x*blockDim.x + threadIdx.x;
    if (i < Bdim*Hdim) { g_hs[i] = 0.0f; g_h[i] = 0.0f; }
}

// ---------------- recurrent step, phase 1: z & r gates --------------------
// [256, 2048] = hs @ [U_z | U_r]; epilogue: z = sig(pre_z + .), rh = sig(pre_r + .)*hs
__global__ void k_zr(const float* __restrict__ Uz, const float* __restrict__ Ur, int t)
{
    __shared__ float4 As[32][16];
    __shared__ float4 Bs[32][16];
    int tid = threadIdx.x;
    int tx = tid & 15, ty = tid >> 4;
    int row0 = blockIdx.y * 64;
    int nblk = blockIdx.x;              // 0..31
    bool is_z = (nblk < 16);
    const float* Um = is_z ? Uz : Ur;
    int col0 = (nblk & 15) * 64;

    float acc[4][4] = {};
    float* Asf = (float*)As;

    for (int kk = 0; kk < Hdim; kk += 32) {
        #pragma unroll
        for (int j = 0; j < 2; j++) {
            int li = tid + 256*j;
            int arow = li >> 3;
            int k4 = (li & 7) * 4;
            float4 a = *(const float4*)(&g_hs[(row0+arow)*Hdim + kk + k4]);
            Asf[(k4+0)*64 + arow] = a.x;
            Asf[(k4+1)*64 + arow] = a.y;
            Asf[(k4+2)*64 + arow] = a.z;
            Asf[(k4+3)*64 + arow] = a.w;
        }
        #pragma unroll
        for (int j = 0; j < 2; j++) {
            int li = tid + 256*j;
            int brow = li >> 4;
            int bc4 = li & 15;
            Bs[brow][bc4] = *(const float4*)(&Um[(kk+brow)*Hdim + col0 + bc4*4]);
        }
        __syncthreads();
        #pragma unroll
        for (int k = 0; k < 32; k++) {
            float4 a = As[k][ty];
            float4 b = Bs[k][tx];
            float av[4] = {a.x,a.y,a.z,a.w};
            float bv[4] = {b.x,b.y,b.z,b.w};
            #pragma unroll
            for (int i = 0; i < 4; i++)
                #pragma unroll
                for (int jj = 0; jj < 4; jj++)
                    acc[i][jj] += av[i]*bv[jj];
        }
        __syncthreads();
    }
    int row = row0 + ty*4;
    int col = col0 + tx*4;
    const float* pre = is_z ? g_pre_z : g_pre_r;
    #pragma unroll
    for (int i = 0; i < 4; i++) {
        #pragma unroll
        for (int jj = 0; jj < 4; jj++) {
            int b = row+i, c = col+jj;
            float v = pre[((size_t)b*Tdim + t)*Hdim + c] + acc[i][jj];
            float s = 1.0f/(1.0f + expf(-v));
            if (is_z) g_z[b*Hdim + c] = s;
            else      g_rh[b*Hdim + c] = s * g_hs[b*Hdim + c];
        }
    }
}

// ---------------- recurrent step, phase 2: candidate + state update -------
// [256,1024] = rh @ U; epilogue: h = (1-z)*hs + z*tanh(pre_h + .); hs_next = gamma_{t+1}*h
__global__ void k_h(const float* __restrict__ Uh, int t)
{
    __shared__ float4 As[32][16];
    __shared__ float4 Bs[32][16];
    int tid = threadIdx.x;
    int tx = tid & 15, ty = tid >> 4;
    int row0 = blockIdx.y * 64;
    int col0 = blockIdx.x * 64;

    float acc[4][4] = {};
    float* Asf = (float*)As;

    for (int kk = 0; kk < Hdim; kk += 32) {
        #pragma unroll
        for (int j = 0; j < 2; j++) {
            int li = tid + 256*j;
            int arow = li >> 3;
            int k4 = (li & 7) * 4;
            float4 a = *(const float4*)(&g_rh[(row0+arow)*Hdim + kk + k4]);
            Asf[(k4+0)*64 + arow] = a.x;
            Asf[(k4+1)*64 + arow] = a.y;
            Asf[(k4+2)*64 + arow] = a.z;
            Asf[(k4+3)*64 + arow] = a.w;
        }
        #pragma unroll
        for (int j = 0; j < 2; j++) {
            int li = tid + 256*j;
            int brow = li >> 4;
            int bc4 = li & 15;
            Bs[brow][bc4] = *(const float4*)(&Uh[(kk+brow)*Hdim + col0 + bc4*4]);
        }
        __syncthreads();
        #pragma unroll
        for (int k = 0; k < 32; k++) {
            float4 a = As[k][ty];
            float4 b = Bs[k][tx];
            float av[4] = {a.x,a.y,a.z,a.w};
            float bv[4] = {b.x,b.y,b.z,b.w};
            #pragma unroll
            for (int i = 0; i < 4; i++)
                #pragma unroll
                for (int jj = 0; jj < 4; jj++)
                    acc[i][jj] += av[i]*bv[jj];
        }
        __syncthreads();
    }
    int row = row0 + ty*4;
    int col = col0 + tx*4;
    #pragma unroll
    for (int i = 0; i < 4; i++) {
        #pragma unroll
        for (int jj = 0; jj < 4; jj++) {
            int b = row+i, c = col+jj;
            int idx = b*Hdim + c;
            float ht = tanhf(g_pre_h[((size_t)b*Tdim + t)*Hdim + c] + acc[i][jj]);
            float hs = g_hs[idx];
            float z  = g_z[idx];
            float hn = (1.0f - z)*hs + z*ht;
            g_h[idx] = hn;
            float gn = (t+1 < Tdim) ? g_gamma[((size_t)b*Tdim + (t+1))*Hdim + c] : 1.0f;
            g_hs[idx] = gn*hn;
        }
    }
}

// ---------------- decoder ---------------------------------------------------
__global__ void k_dec(const float* __restrict__ dW, const float* __restrict__ db,
                      float* __restrict__ out)
{
    __shared__ float hrow[Hdim];
    int b = blockIdx.x;
    for (int i = threadIdx.x; i < Hdim; i += blockDim.x)
        hrow[i] = g_h[b*Hdim + i];
    __syncthreads();
    int o = threadIdx.x;
    float acc = db[o];
    #pragma unroll 8
    for (int k = 0; k < Hdim; k++)
        acc += hrow[k]*dW[k*Odim + o];
    out[b*Odim + o] = acc;
}

// ---------------- launch ----------------------------------------------------
extern "C" void kernel_launch(void* const* d_in, const int* in_sizes, int n_in,
                              void* d_out, int out_size)
{
    const float* x     = (const float*)d_in[0];
    const float* delta = (const float*)d_in[1];
    const float* m     = (const float*)d_in[2];
    const float* W_r   = (const float*)d_in[3];
    const float* U_r   = (const float*)d_in[4];
    const float* V_r   = (const float*)d_in[5];
    const float* b_r   = (const float*)d_in[6];
    const float* W_z   = (const float*)d_in[7];
    const float* U_z   = (const float*)d_in[8];
    const float* V_z   = (const float*)d_in[9];
    const float* b_z   = (const float*)d_in[10];
    const float* W     = (const float*)d_in[11];
    const float* U     = (const float*)d_in[12];
    const float* V     = (const float*)d_in[13];
    const float* b     = (const float*)d_in[14];
    const float* Wgx   = (const float*)d_in[15];
    const float* bgx   = (const float*)d_in[16];
    const float* Wgh   = (const float*)d_in[17];
    const float* bgh   = (const float*)d_in[18];
    const float* decW  = (const float*)d_in[19];
    const float* decb  = (const float*)d_in[20];
    float* out = (float*)d_out;

    k_xmod<<<(BT*Ddim + 255)/256, 256>>>(x, delta, m, Wgx, bgx);
    k_pre<<<dim3(Hdim/64, BT/64, 4), 256>>>(m, W_z, V_z, b_z, W_r, V_r, b_r,
                                            W, V, b, Wgh, bgh);
    k_init<<<(Bdim*Hdim + 255)/256, 256>>>();
    for (int t = 0; t < Tdim; t++) {
        k_zr<<<dim3(32, Bdim/64), 256>>>(U_z, U_r, t);
        k_h <<<dim3(16, Bdim/64), 256>>>(U, t);
    }
    k_dec<<<Bdim, Odim>>>(decW, decb, out);
}